// round 5
// baseline (speedup 1.0000x reference)
#include <cuda_runtime.h>
#include <cstdint>

#define BB 32
#define SS 2048
#define HH 1024
#define D2H 2048

// Scratch (device globals — no allocation allowed)
__device__ float g_wq[BB * HH];          // W(dh) + W_b + U_b
__device__ float g_scores[BB * SS];
__device__ float g_weights[BB * SS];
__device__ float g_part[8 * BB * D2H];

// ---------------------------------------------------------------------------
// Kernel A: wq[b][k] = sum_h dh[b][h] * W_w[k][h] + W_b[k] + U_b[k]
// ---------------------------------------------------------------------------
__global__ void wq_kernel(const float* __restrict__ dh,
                          const float* __restrict__ W_w,
                          const float* __restrict__ W_b,
                          const float* __restrict__ U_b) {
    int b = blockIdx.x;
    int k = blockIdx.y * 128 + threadIdx.x;
    __shared__ float dh_s[HH];
    for (int i = threadIdx.x; i < HH; i += 128) dh_s[i] = dh[b * HH + i];
    __syncthreads();
    const float4* wrow = reinterpret_cast<const float4*>(W_w + (size_t)k * HH);
    const float4* dv   = reinterpret_cast<const float4*>(dh_s);
    float acc = 0.f;
#pragma unroll 8
    for (int i = 0; i < HH / 4; i++) {
        float4 w = wrow[i];
        float4 d = dv[i];
        acc += w.x * d.x + w.y * d.y + w.z * d.z + w.w * d.w;
    }
    g_wq[b * HH + k] = acc + W_b[k] + U_b[k];
}

// ---------------------------------------------------------------------------
// Kernel B: fused GEMM(enc @ U^T) + tanh + V-dot  ->  scores[b][s]
// CTA: 128 rows (one b, one s-tile) x full N=1024 (looped in 8 chunks of 128).
// mma.sync.m16n8k8 tf32, 8 warps as 4(M) x 2(N); warp tile 32x64.
// ---------------------------------------------------------------------------
#define LDA 36   // smem row stride (floats): conflict-free for frag loads

__global__ __launch_bounds__(256, 2)
void score_kernel(const float* __restrict__ enc,
                  const float* __restrict__ U_w,
                  const float* __restrict__ V_w,
                  const float* __restrict__ V_b) {
    __shared__ float A_s[128 * LDA];   // enc tile  [m][k]
    __shared__ float B_s[128 * LDA];   // U_w tile  [n][k]
    __shared__ float wq_s[128];
    __shared__ float V_s[128];
    __shared__ float scores_s[128];

    const int tid  = threadIdx.x;
    const int lane = tid & 31;
    const int warp = tid >> 5;
    const int wm   = warp & 3;    // warp row   (0..3) -> 32 rows each
    const int wn   = warp >> 2;   // warp col   (0..1) -> 64 cols each
    const int gid  = lane >> 2;   // group id   (0..7)
    const int tig  = lane & 3;    // thread-in-group

    const int b     = blockIdx.x >> 4;
    const int stile = blockIdx.x & 15;

    const float* Abase = enc + ((size_t)b * SS + (size_t)stile * 128) * D2H;

    if (tid < 128) scores_s[tid] = 0.f;

    float sp[2][2] = {{0.f, 0.f}, {0.f, 0.f}};   // per-thread partial scores

    for (int nc = 0; nc < 8; nc++) {
        __syncthreads();   // protect wq_s/V_s rewrite vs previous epilogue
        if (tid < 128) {
            wq_s[tid] = g_wq[b * HH + nc * 128 + tid];
            V_s[tid]  = V_w[nc * 128 + tid];
        }

        float acc[2][8][4];
#pragma unroll
        for (int mt = 0; mt < 2; mt++)
#pragma unroll
            for (int nt = 0; nt < 8; nt++)
#pragma unroll
                for (int j = 0; j < 4; j++) acc[mt][nt][j] = 0.f;

        const float* Bbase = U_w + (size_t)(nc * 128) * D2H;

        for (int kc = 0; kc < D2H / 32; kc++) {
            __syncthreads();
            // Load A[128x32], B[128x32] tiles (float4, fully coalesced)
#pragma unroll
            for (int i = 0; i < 4; i++) {
                int idx = tid + i * 256;
                int row = idx >> 3, seg = idx & 7;
                *reinterpret_cast<float4*>(A_s + row * LDA + seg * 4) =
                    *reinterpret_cast<const float4*>(Abase + (size_t)row * D2H + kc * 32 + seg * 4);
                *reinterpret_cast<float4*>(B_s + row * LDA + seg * 4) =
                    *reinterpret_cast<const float4*>(Bbase + (size_t)row * D2H + kc * 32 + seg * 4);
            }
            __syncthreads();

            const uint32_t* Au = reinterpret_cast<const uint32_t*>(A_s);
            const uint32_t* Bu = reinterpret_cast<const uint32_t*>(B_s);
#pragma unroll
            for (int kk = 0; kk < 4; kk++) {
                const int k0 = kk * 8;
                uint32_t af[2][4];
#pragma unroll
                for (int mt = 0; mt < 2; mt++) {
                    int r0 = (wm * 32 + mt * 16 + gid) * LDA + k0 + tig;
                    af[mt][0] = Au[r0];
                    af[mt][1] = Au[r0 + 8 * LDA];
                    af[mt][2] = Au[r0 + 4];
                    af[mt][3] = Au[r0 + 8 * LDA + 4];
                }
                uint32_t bf[8][2];
#pragma unroll
                for (int nt = 0; nt < 8; nt++) {
                    int c0 = (wn * 64 + nt * 8 + gid) * LDA + k0 + tig;
                    bf[nt][0] = Bu[c0];
                    bf[nt][1] = Bu[c0 + 4];
                }
#pragma unroll
                for (int mt = 0; mt < 2; mt++)
#pragma unroll
                    for (int nt = 0; nt < 8; nt++) {
                        asm volatile(
                            "mma.sync.aligned.m16n8k8.row.col.f32.tf32.tf32.f32 "
                            "{%0,%1,%2,%3}, {%4,%5,%6,%7}, {%8,%9}, {%0,%1,%2,%3};"
                            : "+f"(acc[mt][nt][0]), "+f"(acc[mt][nt][1]),
                              "+f"(acc[mt][nt][2]), "+f"(acc[mt][nt][3])
                            : "r"(af[mt][0]), "r"(af[mt][1]),
                              "r"(af[mt][2]), "r"(af[mt][3]),
                              "r"(bf[nt][0]), "r"(bf[nt][1]));
                    }
            }
        }

        // Epilogue: tanh(acc + wq) * V, accumulated per row
#pragma unroll
        for (int mt = 0; mt < 2; mt++)
#pragma unroll
            for (int nt = 0; nt < 8; nt++)
#pragma unroll
                for (int j = 0; j < 4; j++) {
                    int nl = wn * 64 + nt * 8 + 2 * tig + (j & 1);
                    float x = acc[mt][nt][j] + wq_s[nl];
                    float e = __expf(2.f * x);
                    float t = 1.f - 2.f / (e + 1.f);   // exact tanh identity
                    sp[mt][j >> 1] += t * V_s[nl];
                }
    }

    // Reduce partial scores: 4 lanes per group share a row; 2 N-warps share a row
#pragma unroll
    for (int mt = 0; mt < 2; mt++)
#pragma unroll
        for (int rh = 0; rh < 2; rh++) {
            float v = sp[mt][rh];
            v += __shfl_xor_sync(0xffffffffu, v, 1);
            v += __shfl_xor_sync(0xffffffffu, v, 2);
            if (tig == 0)
                atomicAdd(&scores_s[wm * 32 + mt * 16 + rh * 8 + gid], v);
        }
    __syncthreads();
    if (tid < 128)
        g_scores[(size_t)b * SS + stile * 128 + tid] = scores_s[tid] + __ldg(V_b);
}

// ---------------------------------------------------------------------------
// Kernel C: softmax over S per batch
// ---------------------------------------------------------------------------
__global__ void softmax_kernel() {
    int b = blockIdx.x, tid = threadIdx.x;   // 256 threads
    __shared__ float red[256];
    float v[8];
    float mx = -1e30f;
#pragma unroll
    for (int i = 0; i < 8; i++) {
        v[i] = g_scores[b * SS + i * 256 + tid];
        mx = fmaxf(mx, v[i]);
    }
    red[tid] = mx;
    __syncthreads();
    for (int s = 128; s > 0; s >>= 1) {
        if (tid < s) red[tid] = fmaxf(red[tid], red[tid + s]);
        __syncthreads();
    }
    mx = red[0];
    __syncthreads();
    float sum = 0.f;
#pragma unroll
    for (int i = 0; i < 8; i++) {
        v[i] = __expf(v[i] - mx);
        sum += v[i];
    }
    red[tid] = sum;
    __syncthreads();
    for (int s = 128; s > 0; s >>= 1) {
        if (tid < s) red[tid] += red[tid + s];
        __syncthreads();
    }
    float inv = 1.f / red[0];
#pragma unroll
    for (int i = 0; i < 8; i++)
        g_weights[b * SS + i * 256 + tid] = v[i] * inv;
}

// ---------------------------------------------------------------------------
// Kernel D1: partial context over an S-chunk (deterministic, no atomics)
// ---------------------------------------------------------------------------
__global__ void ctx_part_kernel(const float* __restrict__ enc) {
    int bb = blockIdx.x, sc = blockIdx.y, t = threadIdx.x;   // 512 threads
    __shared__ float w_s[256];
    if (t < 256) w_s[t] = g_weights[bb * SS + sc * 256 + t];
    __syncthreads();
    const float4* base =
        reinterpret_cast<const float4*>(enc + ((size_t)bb * SS + (size_t)sc * 256) * D2H);
    float4 acc = make_float4(0.f, 0.f, 0.f, 0.f);
#pragma unroll 4
    for (int s = 0; s < 256; s++) {
        float w = w_s[s];
        float4 e = base[(size_t)s * (D2H / 4) + t];
        acc.x += w * e.x; acc.y += w * e.y;
        acc.z += w * e.z; acc.w += w * e.w;
    }
    *reinterpret_cast<float4*>(g_part + ((size_t)sc * BB + bb) * D2H + t * 4) = acc;
}

// Kernel D2: sum the 8 S-chunk partials -> output [B, 1, 2H]
__global__ void ctx_reduce_kernel(float* __restrict__ out) {
    int i = blockIdx.x * blockDim.x + threadIdx.x;
    float s = 0.f;
#pragma unroll
    for (int sc = 0; sc < 8; sc++) s += g_part[sc * (BB * D2H) + i];
    out[i] = s;
}

// ---------------------------------------------------------------------------
extern "C" void kernel_launch(void* const* d_in, const int* in_sizes, int n_in,
                              void* d_out, int out_size) {
    const float* enc = (const float*)d_in[0];   // [32, 2048, 2048]
    const float* dh  = (const float*)d_in[1];   // [1, 32, 1024]
    const float* W_w = (const float*)d_in[2];   // [1024, 1024]
    const float* W_b = (const float*)d_in[3];   // [1024]
    const float* U_w = (const float*)d_in[4];   // [1024, 2048]
    const float* U_b = (const float*)d_in[5];   // [1024]
    const float* V_w = (const float*)d_in[6];   // [1, 1024]
    const float* V_b = (const float*)d_in[7];   // [1]
    float* out = (float*)d_out;                 // [32, 1, 2048]

    wq_kernel<<<dim3(32, 8), 128>>>(dh, W_w, W_b, U_b);
    score_kernel<<<512, 256>>>(enc, U_w, V_w, V_b);
    softmax_kernel<<<32, 256>>>();
    ctx_part_kernel<<<dim3(32, 8), 512>>>(enc);
    ctx_reduce_kernel<<<128, 512>>>(out);
}